// round 9
// baseline (speedup 1.0000x reference)
#include <cuda_runtime.h>
#include <cuda_bf16.h>
#include <mma.h>
#include <math.h>
#include <stdint.h>

using namespace nvcuda;

#define NTOT 4096
#define NSUP 1024
#define DIM  1024
#define MAXD 1024
#define TOPC 8
#define NITER 96
#define SBLK 32
#define SKW 40                                     // smem row stride (bf16 elems)

// ---------------- device scratch (allocation-free: __device__ globals) ------
__device__ float g_X [(size_t)NTOT * DIM];          // 16 MB fp32 inputs
__device__ __nv_bfloat16 g_Xh[(size_t)NTOT * DIM];  // 8 MB hi
__device__ __nv_bfloat16 g_Xl[(size_t)NTOT * DIM];  // 8 MB lo
__device__ float g_G [(size_t)NTOT * NTOT];         // 64 MB Gram matrix
__device__ float g_sq[NTOT];
__device__ int   g_top8[NTOT * TOPC];
__device__ __align__(16) int g_top4[NTOT * 4];
__device__ int   g_adj[(size_t)NTOT * MAXD];
__device__ int   g_deg[NTOT];
__device__ float g_Wv[(size_t)NTOT * MAXD];
__device__ float g_D[NTOT];
__device__ int2  g_edge[(size_t)NTOT * MAXD];
__device__ float g_y[NTOT * 2];
__device__ float g_xbuf[2][NTOT * 2];
__device__ unsigned g_count;
__device__ volatile unsigned g_gen;

// ---------------- stage 0: concat + bf16 hi/lo split ------------------------
__global__ void k_concat(const float* __restrict__ lab, const float* __restrict__ unlab) {
    size_t nl  = (size_t)NSUP * DIM;
    size_t tot = (size_t)NTOT * DIM;
    for (size_t idx = blockIdx.x * (size_t)blockDim.x + threadIdx.x; idx < tot;
         idx += gridDim.x * (size_t)blockDim.x) {
        float v = (idx < nl) ? lab[idx] : unlab[idx - nl];
        g_X[idx] = v;
        __nv_bfloat16 h = __float2bfloat16_rn(v);
        g_Xh[idx] = h;
        g_Xl[idx] = __float2bfloat16_rn(v - __bfloat162float(h));
    }
}

// ---------------- stage 1: row squared norms --------------------------------
__global__ void k_sq() {
    int i = blockIdx.x, tid = threadIdx.x;
    __shared__ float red[256];
    const float* r = g_X + (size_t)i * DIM;
    float s = 0.f;
    for (int k = tid; k < DIM; k += 256) { float v = r[k]; s += v * v; }
    red[tid] = s; __syncthreads();
    for (int st = 128; st > 0; st >>= 1) {
        if (tid < st) red[tid] += red[tid + st];
        __syncthreads();
    }
    if (tid == 0) g_sq[i] = red[0];
}

// ---------------- stage 2: split-bf16 tensor-core GEMM ----------------------
// G = Xh*Xh^T + Xh*Xl^T + Xl*Xh^T  (upper blocks, mirrored)
__global__ void __launch_bounds__(256) k_gemm() {
    int bi = blockIdx.y, bj = blockIdx.x;
    if (bj < bi) return;
    __shared__ __nv_bfloat16 Ah[128 * SKW];
    __shared__ __nv_bfloat16 Al[128 * SKW];
    __shared__ __nv_bfloat16 Bh[128 * SKW];
    __shared__ __nv_bfloat16 Bl[128 * SKW];

    int tid = threadIdx.x;
    int wid = tid >> 5;
    int rA = bi * 128, rB = bj * 128;
    int warp_m = wid >> 2;                     // 0..1  -> 64-row slab
    int warp_n = wid & 3;                      // 0..3  -> 32-col slab
    int mbase = warp_m * 64, nbase = warp_n * 32;

    wmma::fragment<wmma::accumulator, 16, 16, 16, float> acc[4][2];
    #pragma unroll
    for (int u = 0; u < 4; u++)
        #pragma unroll
        for (int v = 0; v < 2; v++) wmma::fill_fragment(acc[u][v], 0.0f);

    int lrow = tid >> 1;                       // 0..127
    int lhalf = (tid & 1) * 16;                // 0 or 16 (k offset)

    for (int k0 = 0; k0 < DIM; k0 += 32) {
        // load 128x32 tiles of Ah/Al/Bh/Bl (two float4 = 16 bf16 per array/thread)
        const float4* pah = (const float4*)&g_Xh[(size_t)(rA + lrow) * DIM + k0 + lhalf];
        const float4* pal = (const float4*)&g_Xl[(size_t)(rA + lrow) * DIM + k0 + lhalf];
        const float4* pbh = (const float4*)&g_Xh[(size_t)(rB + lrow) * DIM + k0 + lhalf];
        const float4* pbl = (const float4*)&g_Xl[(size_t)(rB + lrow) * DIM + k0 + lhalf];
        float4 vah0 = pah[0], vah1 = pah[1];
        float4 val0 = pal[0], val1 = pal[1];
        float4 vbh0 = pbh[0], vbh1 = pbh[1];
        float4 vbl0 = pbl[0], vbl1 = pbl[1];
        __syncthreads();
        float4* sa = (float4*)&Ah[lrow * SKW + lhalf];
        sa[0] = vah0; sa[1] = vah1;
        float4* sl = (float4*)&Al[lrow * SKW + lhalf];
        sl[0] = val0; sl[1] = val1;
        float4* sb = (float4*)&Bh[lrow * SKW + lhalf];
        sb[0] = vbh0; sb[1] = vbh1;
        float4* sc = (float4*)&Bl[lrow * SKW + lhalf];
        sc[0] = vbl0; sc[1] = vbl1;
        __syncthreads();

        #pragma unroll
        for (int kk = 0; kk < 32; kk += 16) {
            wmma::fragment<wmma::matrix_a, 16, 16, 16, __nv_bfloat16, wmma::row_major> ah[4], al[4];
            wmma::fragment<wmma::matrix_b, 16, 16, 16, __nv_bfloat16, wmma::col_major> bh[2], bl[2];
            #pragma unroll
            for (int u = 0; u < 4; u++) {
                wmma::load_matrix_sync(ah[u], &Ah[(mbase + u * 16) * SKW + kk], SKW);
                wmma::load_matrix_sync(al[u], &Al[(mbase + u * 16) * SKW + kk], SKW);
            }
            #pragma unroll
            for (int v = 0; v < 2; v++) {
                wmma::load_matrix_sync(bh[v], &Bh[(nbase + v * 16) * SKW + kk], SKW);
                wmma::load_matrix_sync(bl[v], &Bl[(nbase + v * 16) * SKW + kk], SKW);
            }
            #pragma unroll
            for (int u = 0; u < 4; u++)
                #pragma unroll
                for (int v = 0; v < 2; v++) {
                    wmma::mma_sync(acc[u][v], ah[u], bh[v], acc[u][v]);
                    wmma::mma_sync(acc[u][v], ah[u], bl[v], acc[u][v]);
                    wmma::mma_sync(acc[u][v], al[u], bh[v], acc[u][v]);
                }
        }
    }

    #pragma unroll
    for (int u = 0; u < 4; u++)
        #pragma unroll
        for (int v = 0; v < 2; v++) {
            int gi = rA + mbase + u * 16;
            int gj = rB + nbase + v * 16;
            wmma::store_matrix_sync(&g_G[(size_t)gi * NTOT + gj], acc[u][v],
                                    NTOT, wmma::mem_row_major);
            if (bi != bj)
                wmma::store_matrix_sync(&g_G[(size_t)gj * NTOT + gi], acc[u][v],
                                        NTOT, wmma::mem_col_major);
        }
}

// ---------------- stage 3: top-8 smallest distances (float4, prefilter) -----
__global__ void k_topk() {
    int i = blockIdx.x, tid = threadIdx.x;
    __shared__ float cd[256 * TOPC];
    __shared__ int   ci[256 * TOPC];
    __shared__ float rd[256];
    __shared__ int   ri[256];
    __shared__ int   rs[256];

    float sqi = g_sq[i];
    const float4* Grow = (const float4*)(g_G + (size_t)i * NTOT);

    float bd[TOPC];
    int   bix[TOPC];
    #pragma unroll
    for (int q = 0; q < TOPC; q++) { bd[q] = INFINITY; bix[q] = 0x7fffffff; }

    for (int j4 = tid; j4 < NTOT / 4; j4 += 256) {
        float4 g = Grow[j4];
        float gv[4] = { g.x, g.y, g.z, g.w };
        #pragma unroll
        for (int e = 0; e < 4; e++) {
            int j = j4 * 4 + e;
            if (j == i) continue;
            float dv = sqi + g_sq[j] - 2.0f * gv[e];
            if (dv < bd[TOPC - 1] || (dv == bd[TOPC - 1] && j < bix[TOPC - 1])) {
                bd[TOPC - 1] = dv; bix[TOPC - 1] = j;
                #pragma unroll
                for (int q = TOPC - 1; q > 0; q--) {
                    if (bd[q] < bd[q - 1] || (bd[q] == bd[q - 1] && bix[q] < bix[q - 1])) {
                        float td = bd[q]; bd[q] = bd[q - 1]; bd[q - 1] = td;
                        int ti = bix[q]; bix[q] = bix[q - 1]; bix[q - 1] = ti;
                    } else break;
                }
            }
        }
    }
    #pragma unroll
    for (int q = 0; q < TOPC; q++) { cd[tid * TOPC + q] = bd[q]; ci[tid * TOPC + q] = bix[q]; }
    __syncthreads();

    for (int round = 0; round < TOPC; round++) {
        float best = INFINITY; int besti = 0x7fffffff; int bslot = -1;
        #pragma unroll
        for (int q = 0; q < TOPC; q++) {
            int slot = tid * TOPC + q;
            float v = cd[slot]; int ix = ci[slot];
            if (v < best || (v == best && ix < besti)) { best = v; besti = ix; bslot = slot; }
        }
        rd[tid] = best; ri[tid] = besti; rs[tid] = bslot;
        __syncthreads();
        for (int st = 128; st > 0; st >>= 1) {
            if (tid < st) {
                if (rd[tid + st] < rd[tid] ||
                    (rd[tid + st] == rd[tid] && ri[tid + st] < ri[tid])) {
                    rd[tid] = rd[tid + st]; ri[tid] = ri[tid + st]; rs[tid] = rs[tid + st];
                }
            }
            __syncthreads();
        }
        if (tid == 0) {
            g_top8[i * TOPC + round] = ri[0];
            cd[rs[0]] = INFINITY; ci[rs[0]] = 0x7fffffff;
        }
        __syncthreads();
    }
}

// ---------------- stage 3b: fp64 refinement of top-8 -> exact top-4 ---------
__global__ void __launch_bounds__(256) k_refine() {
    int i = blockIdx.x;
    int c = threadIdx.x >> 5;                   // candidate 0..7
    int lane = threadIdx.x & 31;
    __shared__ double dd[TOPC];
    __shared__ int    cid[TOPC];

    int j = g_top8[i * TOPC + c];
    const float* xi = g_X + (size_t)i * DIM;
    const float* xj = g_X + (size_t)j * DIM;
    double s = 0.0;
    for (int k = lane; k < DIM; k += 32) {
        double d = (double)xi[k] - (double)xj[k];
        s += d * d;
    }
    #pragma unroll
    for (int o = 16; o > 0; o >>= 1) s += __shfl_down_sync(0xffffffffu, s, o);
    if (lane == 0) { dd[c] = s; cid[c] = j; }
    __syncthreads();
    if (threadIdx.x == 0) {
        bool used[TOPC];
        #pragma unroll
        for (int q = 0; q < TOPC; q++) used[q] = false;
        for (int r = 0; r < 4; r++) {
            int best = -1;
            for (int q = 0; q < TOPC; q++) {
                if (used[q]) continue;
                if (best < 0 || dd[q] < dd[best] ||
                    (dd[q] == dd[best] && cid[q] < cid[best])) best = q;
            }
            used[best] = true;
            g_top4[i * 4 + r] = cid[best];
        }
    }
}

// ---------------- stage 4: deterministic symmetric adjacency ----------------
__global__ void k_adj() {
    int i = blockIdx.x, tid = threadIdx.x;          // 128 threads
    __shared__ int myt[4];
    __shared__ int counts[128];
    __shared__ int offs[128];
    if (tid < 4) myt[tid] = g_top4[i * 4 + tid];
    __syncthreads();
    int t0 = myt[0], t1 = myt[1], t2 = myt[2], t3 = myt[3];

    int local[32]; int cnt = 0;
    int j0 = tid * 32;
    for (int q = 0; q < 32; q++) {
        int j = j0 + q;
        int4 tj = *(const int4*)&g_top4[j * 4];
        bool rev = (tj.x == i) | (tj.y == i) | (tj.z == i) | (tj.w == i);
        if (rev && j != t0 && j != t1 && j != t2 && j != t3) local[cnt++] = j;
    }
    counts[tid] = cnt;
    __syncthreads();
    if (tid == 0) {
        int s = 0;
        for (int k = 0; k < 128; k++) { offs[k] = s; s += counts[k]; }
        int dg = 4 + s;
        g_deg[i] = dg > MAXD ? MAXD : dg;
    }
    __syncthreads();
    int base = 4 + offs[tid];
    for (int q = 0; q < cnt; q++)
        if (base + q < MAXD) g_adj[(size_t)i * MAXD + base + q] = local[q];
    if (tid < 4) g_adj[(size_t)i * MAXD + tid] = myt[tid];
}

// ---------------- stage 5: edge weights + degrees ---------------------------
__global__ void k_weights() {
    int i = blockIdx.x * blockDim.x + threadIdx.x;
    if (i >= NTOT) return;
    int dg = g_deg[i];
    float sqi = g_sq[i];
    float s = 0.f;
    for (int l = 0; l < dg; l++) {
        int j = g_adj[(size_t)i * MAXD + l];
        float dist = (sqi + g_sq[j] - 2.0f * g_G[(size_t)i * NTOT + j]) * (1.0f / 1024.0f);
        float w = expf(-0.5f * dist);          // sigma = 1
        g_Wv[(size_t)i * MAXD + l] = w;
        s += w;
    }
    g_D[i] = s;
}

// ---------------- stage 6: packed edges, alpha * (d_i * W * d_j) ------------
__global__ void k_scale() {
    int i = blockIdx.x * blockDim.x + threadIdx.x;
    if (i >= NTOT) return;
    const float EPSF = 2.220446049250313e-16f;
    int dg = g_deg[i];
    float ri = sqrtf(1.0f / (g_D[i] + EPSF));
    for (int l = 0; l < dg; l++) {
        int j = g_adj[(size_t)i * MAXD + l];
        float rj = sqrtf(1.0f / (g_D[j] + EPSF));
        float sv = 0.99f * ((ri * g_Wv[(size_t)i * MAXD + l]) * rj);
        g_edge[(size_t)i * MAXD + l] = make_int2(j, __float_as_int(sv));
    }
}

// ---------------- stage 7: y (one-hot support labels, int32 targets) --------
__global__ void k_y(const int* __restrict__ tgt) {
    int i = blockIdx.x * blockDim.x + threadIdx.x;
    if (i >= NTOT) return;
    float y0 = 0.f, y1 = 0.f;
    if (i < NSUP) {
        int t = tgt[i];
        y0 = (t == 0) ? 1.f : 0.f;
        y1 = (t == 1) ? 1.f : 0.f;
    }
    g_y[2 * i] = y0;
    g_y[2 * i + 1] = y1;
}

// ---------------- grid barrier (sense-reversing, full publish) ---------------
__device__ __forceinline__ void gridbar() {
    __threadfence();
    __syncthreads();
    if (threadIdx.x == 0) {
        unsigned my = g_gen;
        if (atomicAdd(&g_count, 1) == SBLK - 1) {
            g_count = 0;
            __threadfence();
            g_gen = my + 1;
        } else {
            while (g_gen == my) { __nanosleep(64); }
        }
        __threadfence();
    }
    __syncthreads();
}

// ---------------- stage 8: Chebyshev solve, 32 CTAs, 8 lanes per row --------
__global__ void __launch_bounds__(1024, 1) k_solve(float* __restrict__ out) {
    unsigned gtid = blockIdx.x * 1024u + threadIdx.x;
    int row = gtid >> 3;
    int q8  = gtid & 7;

    const float theta = 1.0f, delta = 0.99f;
    const float sigma = theta / delta;
    float rho_prev = delta / theta;

    float b0 = g_y[2 * row], b1 = g_y[2 * row + 1];
    float d0 = b0, d1 = b1;
    float x0 = b0, x1 = b1;
    int dg = g_deg[row];
    const int2* ep = g_edge + (size_t)row * MAXD;

    if (q8 == 0)
        __stcg((float2*)&g_xbuf[0][2 * row], make_float2(x0, x1));
    gridbar();
    int p = 0;

    for (int it = 1; it < NITER; ++it) {
        float s0 = 0.f, s1 = 0.f;
        for (int l = q8; l < dg; l += 8) {
            int2 e = __ldg(&ep[l]);
            float w = __int_as_float(e.y);
            float2 xj = __ldcg((const float2*)&g_xbuf[p][2 * e.x]);
            s0 += w * xj.x;
            s1 += w * xj.y;
        }
        s0 += __shfl_down_sync(0xffffffffu, s0, 4, 8);
        s1 += __shfl_down_sync(0xffffffffu, s1, 4, 8);
        s0 += __shfl_down_sync(0xffffffffu, s0, 2, 8);
        s1 += __shfl_down_sync(0xffffffffu, s1, 2, 8);
        s0 += __shfl_down_sync(0xffffffffu, s0, 1, 8);
        s1 += __shfl_down_sync(0xffffffffu, s1, 1, 8);

        float rho = 1.0f / (2.0f * sigma - rho_prev);
        float c1 = rho * rho_prev, c2 = 2.0f * rho / delta;
        if (q8 == 0) {
            float rr0 = b0 - x0 + s0;
            float rr1 = b1 - x1 + s1;
            d0 = c1 * d0 + c2 * rr0;
            d1 = c1 * d1 + c2 * rr1;
            x0 += d0;
            x1 += d1;
            if (it != NITER - 1)
                __stcg((float2*)&g_xbuf[1 - p][2 * row], make_float2(x0, x1));
        }
        rho_prev = rho;
        if (it != NITER - 1) {
            gridbar();
            p ^= 1;
        }
    }

    if (q8 == 0 && row >= NSUP) {
        out[2 * (row - NSUP)]     = x0;
        out[2 * (row - NSUP) + 1] = x1;
    }
}

// ---------------- launch -----------------------------------------------------
extern "C" void kernel_launch(void* const* d_in, const int* in_sizes, int n_in,
                              void* d_out, int out_size) {
    const float* lab   = (const float*)d_in[0];
    const int*   tgt   = (const int*)d_in[1];
    const float* unlab = (const float*)d_in[2];
    float* out = (float*)d_out;

    k_concat<<<512, 256>>>(lab, unlab);
    k_sq<<<NTOT, 256>>>();
    dim3 gg(32, 32);
    k_gemm<<<gg, 256>>>();
    k_topk<<<NTOT, 256>>>();
    k_refine<<<NTOT, 256>>>();
    k_adj<<<NTOT, 128>>>();
    k_weights<<<(NTOT + 255) / 256, 256>>>();
    k_scale<<<(NTOT + 255) / 256, 256>>>();
    k_y<<<(NTOT + 255) / 256, 256>>>(tgt);
    k_solve<<<SBLK, 1024>>>(out);
}